// round 1
// baseline (speedup 1.0000x reference)
#include <cuda_runtime.h>
#include <math.h>

// Problem constants
#define BATCH   128
#define N0      512
#define E_TOT   262144   // 128 * 2048
#define F       128      // feature dim everywhere
#define NMAX    65536    // B*N0

// ---------------- static scratch (allocation-free) ----------------
__device__ float g_bufA[NMAX * F];
__device__ float g_bufB[NMAX * F];
__device__ float g_deg[NMAX];
__device__ float g_dinv[NMAX];
__device__ float g_score[NMAX];
__device__ int   g_newid[NMAX];
__device__ int   g_perm[NMAX / 2];
__device__ float g_tanh[NMAX / 2];
__device__ int   g_srcA[E_TOT], g_dstA[E_TOT];
__device__ int   g_srcB[E_TOT], g_dstB[E_TOT];
__device__ unsigned char g_ewA[E_TOT], g_ewB[E_TOT];
__device__ float g_z[BATCH * 2 * F];

// ---------------- kernels ----------------

// Y[n][128] = X[n][128] @ W[128][128], 64x64 block tile, 4x4 per-thread tile
__global__ void k_matmul(const float* __restrict__ X, const float* __restrict__ W,
                         float* __restrict__ Y) {
    __shared__ float Xs[32 * 68];  // [k][row], padded
    __shared__ float Ws[32 * 64];  // [k][col]
    const int rb = blockIdx.x * 64;
    const int cb = blockIdx.y * 64;
    const int tid = threadIdx.x;
    const int tx = tid & 15;   // col group
    const int ty = tid >> 4;   // row group
    float acc[4][4];
#pragma unroll
    for (int i = 0; i < 4; i++)
#pragma unroll
        for (int j = 0; j < 4; j++) acc[i][j] = 0.f;

    for (int kb = 0; kb < 128; kb += 32) {
        // load X tile 64 rows x 32 k (coalesced reads)
#pragma unroll
        for (int i = tid; i < 64 * 32; i += 256) {
            int r = i >> 5, k = i & 31;
            Xs[k * 68 + r] = X[(rb + r) * 128 + kb + k];
        }
        // load W tile 32 k x 64 cols
#pragma unroll
        for (int i = tid; i < 32 * 64; i += 256) {
            int k = i >> 6, c = i & 63;
            Ws[k * 64 + c] = W[(kb + k) * 128 + cb + c];
        }
        __syncthreads();
#pragma unroll
        for (int k = 0; k < 32; k++) {
            float4 xv = *(const float4*)&Xs[k * 68 + ty * 4];
            float4 wv = *(const float4*)&Ws[k * 64 + tx * 4];
            acc[0][0] += xv.x * wv.x; acc[0][1] += xv.x * wv.y; acc[0][2] += xv.x * wv.z; acc[0][3] += xv.x * wv.w;
            acc[1][0] += xv.y * wv.x; acc[1][1] += xv.y * wv.y; acc[1][2] += xv.y * wv.z; acc[1][3] += xv.y * wv.w;
            acc[2][0] += xv.z * wv.x; acc[2][1] += xv.z * wv.y; acc[2][2] += xv.z * wv.z; acc[2][3] += xv.z * wv.w;
            acc[3][0] += xv.w * wv.x; acc[3][1] += xv.w * wv.y; acc[3][2] += xv.w * wv.z; acc[3][3] += xv.w * wv.w;
        }
        __syncthreads();
    }
#pragma unroll
    for (int i = 0; i < 4; i++) {
        float4 v = make_float4(acc[i][0], acc[i][1], acc[i][2], acc[i][3]);
        *(float4*)&Y[(rb + ty * 4 + i) * 128 + cb + tx * 4] = v;
    }
}

__global__ void k_fill_deg(float* deg, int n) {
    int i = blockIdx.x * blockDim.x + threadIdx.x;
    if (i < n) deg[i] = 1.0f;
}

__global__ void k_deg_edges(const int* __restrict__ dst, const unsigned char* __restrict__ ew,
                            float* deg) {
    int e = blockIdx.x * blockDim.x + threadIdx.x;
    if (e >= E_TOT) return;
    if (ew && !ew[e]) return;
    atomicAdd(&deg[dst[e]], 1.0f);
}

__global__ void k_dinv(const float* deg, float* dinv, int n) {
    int i = blockIdx.x * blockDim.x + threadIdx.x;
    if (i < n) dinv[i] = rsqrtf(deg[i]);
}

// agg[i][f] = hW[i][f]*dinv[i]^2 + b[f]
__global__ void k_agg_init(const float* __restrict__ hW, const float* __restrict__ b,
                           const float* __restrict__ dinv, float* __restrict__ agg, int n) {
    int idx = blockIdx.x * blockDim.x + threadIdx.x;
    if (idx >= n * F) return;
    int i = idx >> 7, f = idx & 127;
    float d = dinv[i];
    agg[idx] = hW[idx] * d * d + b[f];
}

// one warp per edge: agg[dst] += hW[src] * dinv[s]*dinv[d]  (ew implicit 1 if null)
__global__ void k_msg(const float* __restrict__ hW, const int* __restrict__ src,
                      const int* __restrict__ dst, const unsigned char* __restrict__ ew,
                      const float* __restrict__ dinv, float* __restrict__ agg) {
    int gt = blockIdx.x * blockDim.x + threadIdx.x;
    int e = gt >> 5, lane = gt & 31;
    if (e >= E_TOT) return;
    if (ew && !ew[e]) return;
    int s = src[e], d = dst[e];
    float c = dinv[s] * dinv[d];
    const float* hs = hW + (long long)s * F;
    float* ad = agg + (long long)d * F;
#pragma unroll
    for (int f = lane; f < F; f += 32) atomicAdd(&ad[f], hs[f] * c);
}

__global__ void k_relu(float* a, int n) {
    int i = blockIdx.x * blockDim.x + threadIdx.x;
    if (i < n) a[i] = fmaxf(a[i], 0.f);
}

// score[i] = (h[i] . p) / ||p||   — 4 warps/block, 1 node/warp
__global__ void k_score(const float* __restrict__ h, const float* __restrict__ p,
                        float* __restrict__ score, int n) {
    __shared__ float invn;
    int tid = threadIdx.x, lane = tid & 31, w = tid >> 5;
    if (tid == 0) {
        float s = 0.f;
        for (int i = 0; i < F; i++) { float v = p[i]; s += v * v; }
        invn = rsqrtf(s);
    }
    __syncthreads();
    int node = blockIdx.x * 4 + w;
    if (node >= n) return;
    float s = 0.f;
#pragma unroll
    for (int f = lane; f < F; f += 32) s += h[node * F + f] * p[f];
#pragma unroll
    for (int o = 16; o > 0; o >>= 1) s += __shfl_down_sync(0xffffffffu, s, o);
    if (lane == 0) score[node] = s * invn;
}

// per-graph bitonic top-k: block = graph, blockDim = n_per (pow2, <=512)
// sorts by (score desc, idx asc) to match jax.lax.top_k tie semantics
__global__ void k_topk(const float* __restrict__ score, int n_per, int k,
                       int* __restrict__ perm, int* __restrict__ new_id,
                       float* __restrict__ tanhv) {
    __shared__ float sc[512];
    __shared__ int id[512];
    int b = blockIdx.x, tid = threadIdx.x;
    int base = b * n_per;
    sc[tid] = score[base + tid];
    id[tid] = tid;
    new_id[base + tid] = -1;
    __syncthreads();
    for (int kk = 2; kk <= n_per; kk <<= 1) {
        for (int j = kk >> 1; j > 0; j >>= 1) {
            int ixj = tid ^ j;
            if (ixj > tid) {
                bool dir = ((tid & kk) == 0);
                float s1 = sc[tid], s2 = sc[ixj];
                int i1 = id[tid], i2 = id[ixj];
                // earlier(a,b): a.s>b.s || (a.s==b.s && a.i<b.i)
                bool swp = dir ? ((s2 > s1) || (s2 == s1 && i2 < i1))
                               : ((s1 > s2) || (s1 == s2 && i1 < i2));
                if (swp) { sc[tid] = s2; sc[ixj] = s1; id[tid] = i2; id[ixj] = i1; }
            }
            __syncthreads();
        }
    }
    if (tid < k) {
        int g = base + id[tid];
        perm[b * k + tid] = g;
        new_id[g] = b * k + tid;
        tanhv[b * k + tid] = tanhf(sc[tid]);
    }
}

// xk[j] = h[perm[j]] * tanhv[j]
__global__ void k_gather(float* __restrict__ xk, const float* __restrict__ h,
                         const int* __restrict__ perm, const float* __restrict__ tanhv) {
    int j = blockIdx.x, f = threadIdx.x;
    xk[j * F + f] = h[perm[j] * F + f] * tanhv[j];
}

__global__ void k_relabel(const int* __restrict__ srcI, const int* __restrict__ dstI,
                          const unsigned char* __restrict__ ewI, const int* __restrict__ new_id,
                          int* __restrict__ srcO, int* __restrict__ dstO,
                          unsigned char* __restrict__ ewO) {
    int e = blockIdx.x * blockDim.x + threadIdx.x;
    if (e >= E_TOT) return;
    int keep = ewI ? (int)ewI[e] : 1;
    int ns = 0, nd = 0;
    if (keep) {
        ns = new_id[srcI[e]];
        nd = new_id[dstI[e]];
        keep = (ns >= 0) && (nd >= 0);
    }
    srcO[e] = keep ? ns : 0;
    dstO[e] = keep ? nd : 0;
    ewO[e] = (unsigned char)keep;
}

// z[b][f] (=|+=) max over k nodes; z[b][128+f] (=|+=) mean
__global__ void k_readout(const float* __restrict__ x, float* __restrict__ z, int k, int acc) {
    int b = blockIdx.x, f = threadIdx.x;
    const float* xb = x + (long long)b * k * F;
    float mx = -INFINITY, sm = 0.f;
    for (int j = 0; j < k; j++) {
        float v = xb[j * F + f];
        mx = fmaxf(mx, v);
        sm += v;
    }
    sm *= (1.0f / (float)k);
    if (acc) {
        z[b * 256 + f] += mx;
        z[b * 256 + 128 + f] += sm;
    } else {
        z[b * 256 + f] = mx;
        z[b * 256 + 128 + f] = sm;
    }
}

// final MLP + log_softmax, one block per batch row
__global__ void k_mlp(const float* __restrict__ z,
                      const float* __restrict__ L1, const float* __restrict__ bl1,
                      const float* __restrict__ L2, const float* __restrict__ bl2,
                      const float* __restrict__ L3, const float* __restrict__ bl3,
                      float* __restrict__ out) {
    __shared__ float zr[256];
    __shared__ float h1[128];
    __shared__ float h2[64];
    __shared__ float lg[2];
    int b = blockIdx.x, tid = threadIdx.x;
    zr[tid] = z[b * 256 + tid];
    zr[128 + tid] = z[b * 256 + 128 + tid];
    __syncthreads();
    float a = bl1[tid];
    for (int i = 0; i < 256; i++) a += zr[i] * L1[i * 128 + tid];
    h1[tid] = fmaxf(a, 0.f);
    __syncthreads();
    if (tid < 64) {
        float a2 = bl2[tid];
        for (int i = 0; i < 128; i++) a2 += h1[i] * L2[i * 64 + tid];
        h2[tid] = fmaxf(a2, 0.f);
    }
    __syncthreads();
    if (tid < 2) {
        float a3 = bl3[tid];
        for (int i = 0; i < 64; i++) a3 += h2[i] * L3[i * 2 + tid];
        lg[tid] = a3;
    }
    __syncthreads();
    if (tid == 0) {
        float m = fmaxf(lg[0], lg[1]);
        float lse = m + logf(expf(lg[0] - m) + expf(lg[1] - m));
        out[b * 2 + 0] = lg[0] - lse;
        out[b * 2 + 1] = lg[1] - lse;
    }
}

// ---------------- host orchestration ----------------
extern "C" void kernel_launch(void* const* d_in, const int* in_sizes, int n_in,
                              void* d_out, int out_size) {
    const float* x   = (const float*)d_in[0];
    const int*   src = (const int*)d_in[1];
    const int*   dst = (const int*)d_in[2];
    const float* W1 = (const float*)d_in[3];  const float* b1 = (const float*)d_in[4];
    const float* W2 = (const float*)d_in[5];  const float* b2 = (const float*)d_in[6];
    const float* W3 = (const float*)d_in[7];  const float* b3 = (const float*)d_in[8];
    const float* p1 = (const float*)d_in[9];
    const float* p2 = (const float*)d_in[10];
    const float* p3 = (const float*)d_in[11];
    const float* L1 = (const float*)d_in[12]; const float* bl1 = (const float*)d_in[13];
    const float* L2 = (const float*)d_in[14]; const float* bl2 = (const float*)d_in[15];
    const float* L3 = (const float*)d_in[16]; const float* bl3 = (const float*)d_in[17];
    float* out = (float*)d_out;

    float *A, *B, *deg, *dinv, *score, *tanhv, *z;
    int *newid, *perm, *srcA, *dstA, *srcB, *dstB;
    unsigned char *ewA, *ewB;
    cudaGetSymbolAddress((void**)&A, g_bufA);
    cudaGetSymbolAddress((void**)&B, g_bufB);
    cudaGetSymbolAddress((void**)&deg, g_deg);
    cudaGetSymbolAddress((void**)&dinv, g_dinv);
    cudaGetSymbolAddress((void**)&score, g_score);
    cudaGetSymbolAddress((void**)&newid, g_newid);
    cudaGetSymbolAddress((void**)&perm, g_perm);
    cudaGetSymbolAddress((void**)&tanhv, g_tanh);
    cudaGetSymbolAddress((void**)&srcA, g_srcA);
    cudaGetSymbolAddress((void**)&dstA, g_dstA);
    cudaGetSymbolAddress((void**)&srcB, g_srcB);
    cudaGetSymbolAddress((void**)&dstB, g_dstB);
    cudaGetSymbolAddress((void**)&ewA, g_ewA);
    cudaGetSymbolAddress((void**)&ewB, g_ewB);
    cudaGetSymbolAddress((void**)&z, g_z);

    const int EB = 256, EG = E_TOT / EB;

    // ---------- stage 1: n=65536, n_per=512, k=256 ----------
    {
        const int n = 65536, n_per = 512, k = 256;
        k_matmul<<<dim3(n / 64, 2), 256>>>(x, W1, A);
        k_fill_deg<<<(n + 255) / 256, 256>>>(deg, n);
        k_deg_edges<<<EG, EB>>>(dst, nullptr, deg);
        k_dinv<<<(n + 255) / 256, 256>>>(deg, dinv, n);
        k_agg_init<<<(n * F) / 256, 256>>>(A, b1, dinv, B, n);
        k_msg<<<E_TOT / 8, 256>>>(A, src, dst, nullptr, dinv, B);
        k_relu<<<(n * F) / 256, 256>>>(B, n * F);
        k_score<<<n / 4, 128>>>(B, p1, score, n);
        k_topk<<<BATCH, n_per>>>(score, n_per, k, perm, newid, tanhv);
        k_gather<<<BATCH * k, F>>>(A, B, perm, tanhv);
        k_relabel<<<EG, EB>>>(src, dst, nullptr, newid, srcA, dstA, ewA);
        k_readout<<<BATCH, F>>>(A, z, k, 0);
    }
    // ---------- stage 2: n=32768, n_per=256, k=128 ----------
    {
        const int n = 32768, n_per = 256, k = 128;
        k_matmul<<<dim3(n / 64, 2), 256>>>(A, W2, B);
        k_fill_deg<<<(n + 255) / 256, 256>>>(deg, n);
        k_deg_edges<<<EG, EB>>>(dstA, ewA, deg);
        k_dinv<<<(n + 255) / 256, 256>>>(deg, dinv, n);
        k_agg_init<<<(n * F) / 256, 256>>>(B, b2, dinv, A, n);
        k_msg<<<E_TOT / 8, 256>>>(B, srcA, dstA, ewA, dinv, A);
        k_relu<<<(n * F) / 256, 256>>>(A, n * F);
        k_score<<<n / 4, 128>>>(A, p2, score, n);
        k_topk<<<BATCH, n_per>>>(score, n_per, k, perm, newid, tanhv);
        k_gather<<<BATCH * k, F>>>(B, A, perm, tanhv);
        k_relabel<<<EG, EB>>>(srcA, dstA, ewA, newid, srcB, dstB, ewB);
        k_readout<<<BATCH, F>>>(B, z, k, 1);
    }
    // ---------- stage 3: n=16384, n_per=128, k=64 ----------
    {
        const int n = 16384, n_per = 128, k = 64;
        k_matmul<<<dim3(n / 64, 2), 256>>>(B, W3, A);
        k_fill_deg<<<(n + 255) / 256, 256>>>(deg, n);
        k_deg_edges<<<EG, EB>>>(dstB, ewB, deg);
        k_dinv<<<(n + 255) / 256, 256>>>(deg, dinv, n);
        k_agg_init<<<(n * F) / 256, 256>>>(A, b3, dinv, B, n);
        k_msg<<<E_TOT / 8, 256>>>(A, srcB, dstB, ewB, dinv, B);
        k_relu<<<(n * F) / 256, 256>>>(B, n * F);
        k_score<<<n / 4, 128>>>(B, p3, score, n);
        k_topk<<<BATCH, n_per>>>(score, n_per, k, perm, newid, tanhv);
        k_gather<<<BATCH * k, F>>>(A, B, perm, tanhv);
        // pool-3 edge relabel is dead in the reference — skipped
        k_readout<<<BATCH, F>>>(A, z, k, 1);
    }
    // ---------- MLP head ----------
    k_mlp<<<BATCH, 128>>>(z, L1, bl1, L2, bl2, L3, bl3, out);
}